// round 7
// baseline (speedup 1.0000x reference)
#include <cuda_runtime.h>
#include <cuda_fp16.h>
#include <math.h>
#include <cstdint>

// ---------------- problem constants ----------------
#define T_TOK   8192
#define H_DIM   2048
#define N_EXP   32
#define TOPK    6
#define M_DIM   1408
#define SH_DIM  2816
#define TK      (T_TOK * TOPK)   // 49152

// ---------------- scratch (device globals) ----------------
__device__ __half g_xh[(size_t)T_TOK * H_DIM];            // fp16 x
__device__ __half g_wguh[(size_t)N_EXP * H_DIM * 2 * M_DIM];  // interleaved gate|up weights
__device__ __half g_wdh[(size_t)N_EXP * M_DIM * H_DIM];
__device__ __half g_swguh[(size_t)H_DIM * 2 * SH_DIM];    // interleaved shared gate|up
__device__ __half g_swdh[(size_t)SH_DIM * H_DIM];
__device__ __half g_hr[(size_t)TK * M_DIM];               // routed silu(g)*u
__device__ __half g_dout[(size_t)TK * H_DIM];             // routed down out (fp16)
__device__ __half g_hs[(size_t)T_TOK * SH_DIM];           // shared silu(g)*u
__device__ float  g_scores[T_TOK * N_EXP];
__device__ int    g_sel[TK];
__device__ float  g_selw[TK];
__device__ int    g_counts[N_EXP];
__device__ int    g_offsets[N_EXP + 1];
__device__ int    g_fill[N_EXP];
__device__ int    g_toklist[TK];
__device__ int    g_pos[TK];

// ---------------- PTX helpers ----------------
__device__ __forceinline__ uint32_t smem_u32(const void* p) {
    uint32_t a;
    asm("{ .reg .u64 t; cvta.to.shared.u64 t, %1; cvt.u32.u64 %0, t; }" : "=r"(a) : "l"(p));
    return a;
}
#define CP16(dst, src)  asm volatile("cp.async.cg.shared.global [%0], [%1], 16;" :: "r"(dst), "l"(src) : "memory")
#define CP_COMMIT()     asm volatile("cp.async.commit_group;" ::: "memory")

__device__ __forceinline__ void ldsm4(uint32_t* r, uint32_t addr) {
    asm volatile("ldmatrix.sync.aligned.m8n8.x4.shared.b16 {%0,%1,%2,%3}, [%4];"
                 : "=r"(r[0]), "=r"(r[1]), "=r"(r[2]), "=r"(r[3]) : "r"(addr));
}
__device__ __forceinline__ void ldsm4t(uint32_t* r, uint32_t addr) {
    asm volatile("ldmatrix.sync.aligned.m8n8.x4.trans.shared.b16 {%0,%1,%2,%3}, [%4];"
                 : "=r"(r[0]), "=r"(r[1]), "=r"(r[2]), "=r"(r[3]) : "r"(addr));
}
__device__ __forceinline__ void mma_f16(float* d, const uint32_t* a, const uint32_t* b) {
    asm volatile("mma.sync.aligned.m16n8k16.row.col.f32.f16.f16.f32 "
                 "{%0,%1,%2,%3}, {%4,%5,%6,%7}, {%8,%9}, {%0,%1,%2,%3};"
                 : "+f"(d[0]), "+f"(d[1]), "+f"(d[2]), "+f"(d[3])
                 : "r"(a[0]), "r"(a[1]), "r"(a[2]), "r"(a[3]), "r"(b[0]), "r"(b[1]));
}
__device__ __forceinline__ float silu_mul(float g, float u) {
    return g / (1.f + expf(-g)) * u;
}

// ---------------- small kernels ----------------
__global__ void reset_kernel() {
    int i = threadIdx.x;
    if (i < N_EXP) { g_counts[i] = 0; g_fill[i] = 0; }
}

// fp32 -> fp16, 16 elems/thread (n divisible by 4096)
__global__ void cvt_f2h(const float* __restrict__ in, __half* __restrict__ out) {
    size_t i = ((size_t)blockIdx.x * blockDim.x + threadIdx.x) * 16;
    float4 v0 = *(const float4*)(in + i);
    float4 v1 = *(const float4*)(in + i + 4);
    float4 v2 = *(const float4*)(in + i + 8);
    float4 v3 = *(const float4*)(in + i + 12);
    __half2 h[8];
    h[0] = __floats2half2_rn(v0.x, v0.y); h[1] = __floats2half2_rn(v0.z, v0.w);
    h[2] = __floats2half2_rn(v1.x, v1.y); h[3] = __floats2half2_rn(v1.z, v1.w);
    h[4] = __floats2half2_rn(v2.x, v2.y); h[5] = __floats2half2_rn(v2.z, v2.w);
    h[6] = __floats2half2_rn(v3.x, v3.y); h[7] = __floats2half2_rn(v3.z, v3.w);
    *(uint4*)(out + i)     = *(uint4*)h;
    *(uint4*)(out + i + 8) = *(uint4*)(h + 4);
}

// interleave: out[2i]=a[i], out[2i+1]=b[i] as fp16, 16 inputs/thread
__global__ void cvt_interleave(const float* __restrict__ a, const float* __restrict__ b,
                               __half* __restrict__ out) {
    size_t i = ((size_t)blockIdx.x * blockDim.x + threadIdx.x) * 16;
    float4 a0 = *(const float4*)(a + i),     a1 = *(const float4*)(a + i + 4);
    float4 a2 = *(const float4*)(a + i + 8), a3 = *(const float4*)(a + i + 12);
    float4 b0 = *(const float4*)(b + i),     b1 = *(const float4*)(b + i + 4);
    float4 b2 = *(const float4*)(b + i + 8), b3 = *(const float4*)(b + i + 12);
    __half2 h[16];
    h[0]  = __floats2half2_rn(a0.x, b0.x); h[1]  = __floats2half2_rn(a0.y, b0.y);
    h[2]  = __floats2half2_rn(a0.z, b0.z); h[3]  = __floats2half2_rn(a0.w, b0.w);
    h[4]  = __floats2half2_rn(a1.x, b1.x); h[5]  = __floats2half2_rn(a1.y, b1.y);
    h[6]  = __floats2half2_rn(a1.z, b1.z); h[7]  = __floats2half2_rn(a1.w, b1.w);
    h[8]  = __floats2half2_rn(a2.x, b2.x); h[9]  = __floats2half2_rn(a2.y, b2.y);
    h[10] = __floats2half2_rn(a2.z, b2.z); h[11] = __floats2half2_rn(a2.w, b2.w);
    h[12] = __floats2half2_rn(a3.x, b3.x); h[13] = __floats2half2_rn(a3.y, b3.y);
    h[14] = __floats2half2_rn(a3.z, b3.z); h[15] = __floats2half2_rn(a3.w, b3.w);
    *(uint4*)(out + 2 * i)      = *(uint4*)(h);
    *(uint4*)(out + 2 * i + 8)  = *(uint4*)(h + 4);
    *(uint4*)(out + 2 * i + 16) = *(uint4*)(h + 8);
    *(uint4*)(out + 2 * i + 24) = *(uint4*)(h + 12);
}

__global__ void gate_kernel(const float* __restrict__ x, const float* __restrict__ gw) {
    int warp = (blockIdx.x * blockDim.x + threadIdx.x) >> 5;
    int lane = threadIdx.x & 31;
    if (warp >= T_TOK) return;
    const float* xr = x + (size_t)warp * H_DIM;
    float acc = 0.f;
#pragma unroll 4
    for (int h = 0; h < H_DIM; h += 4) {
        float4 xv = *(const float4*)(xr + h);
        acc += xv.x * gw[(h + 0) * N_EXP + lane];
        acc += xv.y * gw[(h + 1) * N_EXP + lane];
        acc += xv.z * gw[(h + 2) * N_EXP + lane];
        acc += xv.w * gw[(h + 3) * N_EXP + lane];
    }
    g_scores[warp * N_EXP + lane] = 1.f / (1.f + expf(-acc));
}

__global__ void route_kernel() {
    int t = blockIdx.x * blockDim.x + threadIdx.x;
    if (t >= T_TOK) return;
    float sc[N_EXP];
#pragma unroll
    for (int e = 0; e < N_EXP; e++) sc[e] = g_scores[t * N_EXP + e];
    float gm[4];
#pragma unroll
    for (int g = 0; g < 4; g++) {
        float m = sc[g * 8];
#pragma unroll
        for (int j = 1; j < 8; j++) m = fmaxf(m, sc[g * 8 + j]);
        gm[g] = m;
    }
    int g1 = 0;
#pragma unroll
    for (int g = 1; g < 4; g++) if (gm[g] > gm[g1]) g1 = g;
    int g2 = (g1 == 0) ? 1 : 0;
#pragma unroll
    for (int g = 0; g < 4; g++) if (g != g1 && gm[g] > gm[g2]) g2 = g;
    unsigned allowed = 0;
#pragma unroll
    for (int e = 0; e < N_EXP; e++) {
        int g = e >> 3;
        if (g == g1 || g == g2) allowed |= (1u << e);
    }
    unsigned picked = 0;
    float wsum = 0.f;
    int etmp[TOPK]; float wtmp[TOPK];
#pragma unroll
    for (int k = 0; k < TOPK; k++) {
        int best = -1; float bv = -1.f;
#pragma unroll
        for (int e = 0; e < N_EXP; e++) {
            if (!((allowed >> e) & 1u)) continue;
            if ((picked >> e) & 1u) continue;
            if (sc[e] > bv) { bv = sc[e]; best = e; }
        }
        picked |= (1u << best);
        etmp[k] = best; wtmp[k] = bv; wsum += bv;
    }
    float inv = 1.f / wsum;
#pragma unroll
    for (int k = 0; k < TOPK; k++) {
        g_sel[t * TOPK + k]  = etmp[k];
        g_selw[t * TOPK + k] = wtmp[k] * inv;
        atomicAdd(&g_counts[etmp[k]], 1);
    }
}

__global__ void scan_kernel() {
    if (threadIdx.x == 0) {
        int s = 0;
        for (int e = 0; e < N_EXP; e++) { g_offsets[e] = s; s += g_counts[e]; }
        g_offsets[N_EXP] = s;
    }
}

__global__ void scatter_kernel() {
    int i = blockIdx.x * blockDim.x + threadIdx.x;
    if (i >= TK) return;
    int e = g_sel[i];
    int p = g_offsets[e] + atomicAdd(&g_fill[e], 1);
    g_toklist[p] = i / TOPK;
    g_pos[i] = p;
}

// combine: out[t] += sum_k w_k * dout_fp16[pos_k]
__global__ void combine_kernel(float* __restrict__ out) {
    int t = blockIdx.x;
    float w[TOPK]; int ps[TOPK];
#pragma unroll
    for (int k = 0; k < TOPK; k++) { w[k] = g_selw[t * TOPK + k]; ps[k] = g_pos[t * TOPK + k]; }
    for (int h2 = threadIdx.x; h2 < H_DIM / 2; h2 += blockDim.x) {
        float2 acc = *(float2*)(out + (size_t)t * H_DIM + h2 * 2);
#pragma unroll
        for (int k = 0; k < TOPK; k++) {
            float2 v = __half22float2(*(const __half2*)(g_dout + (size_t)ps[k] * H_DIM + h2 * 2));
            acc.x += w[k] * v.x; acc.y += w[k] * v.y;
        }
        *(float2*)(out + (size_t)t * H_DIM + h2 * 2) = acc;
    }
}

// ---------------- FP16 mma.sync GEMM ----------------
// C[row][n] = sum_k A[arow][k] * B[k][n]
// Tile 128x256x32, 8 warps (2x4 grid, 64x64 warp tiles), 6-stage cp.async pipeline.
#define BM 128
#define BN 256
#define BK 32
#define NTHR 256
#define ASTR 40      // halves per A smem row (64B data + 16B pad)
#define BSTR 264     // halves per B smem row (512B data + 16B pad)
#define A_BYTES (BM * ASTR * 2)          // 10240
#define B_BYTES (BK * BSTR * 2)          // 16896
#define STAGEB  (A_BYTES + B_BYTES)      // 27136
#define NSTAGE 6
#define SMEM_BYTES (NSTAGE * STAGEB)     // 162816

#define EPI_F  0
#define EPI_H  1
#define EPI_SP 2

template <bool EXPERT, bool GATHER, int EPI>
__global__ void __launch_bounds__(NTHR, 1)
hgemm(const __half* __restrict__ A, const __half* __restrict__ B0,
      void* __restrict__ Cv, int rowsTotal, int N, int K) {
    int e = EXPERT ? blockIdx.z : 0;
    int base = 0, cnt;
    if (EXPERT) { base = g_offsets[e]; cnt = g_offsets[e + 1] - base; }
    else        cnt = rowsTotal;
    int row0 = blockIdx.y * BM;
    if (row0 >= cnt) return;
    int n0 = blockIdx.x * BN;
    const __half* B = EXPERT ? B0 + (size_t)e * K * N : B0;
    const int Cw = (EPI == EPI_SP) ? (N >> 1) : N;

    extern __shared__ char smem[];
    uint32_t s0 = smem_u32(smem);

    int tid = threadIdx.x, wid = tid >> 5, lane = tid & 31;
    int wm = wid >> 2, wn = wid & 3;     // 2x4 warp grid, 64x64 warp tile

    // ---- hoisted loader addresses ----
    // A: 512 chunks (128 rows x 4), 2 per thread; B: 1024 chunks (32 rows x 32), 4 per thread
    const __half* aptr[2]; uint32_t adst[2];
    const __half* bptr[4]; uint32_t bdst[4];
#pragma unroll
    for (int it = 0; it < 2; it++) {
        int i = tid + it * NTHR;
        int row = i >> 2, ch = i & 3;
        int r = min(row0 + row, cnt - 1);
        int arow = GATHER ? g_toklist[base + r] : (base + r);
        aptr[it] = A + (size_t)arow * K + ch * 8;
        adst[it] = (uint32_t)(row * ASTR + ch * 8) * 2;
    }
#pragma unroll
    for (int it = 0; it < 4; it++) {
        int i = tid + it * NTHR;
        int krow = i >> 5, ch = i & 31;
        bptr[it] = B + (size_t)krow * N + n0 + ch * 8;
        bdst[it] = (uint32_t)(krow * BSTR + ch * 8) * 2;
    }

    float acc[4][8][4];
#pragma unroll
    for (int mf = 0; mf < 4; mf++)
#pragma unroll
        for (int nf = 0; nf < 8; nf++)
#pragma unroll
            for (int q = 0; q < 4; q++) acc[mf][nf][q] = 0.f;

    const int nch = K / BK;

    auto load_stage = [&](int c, int s) {
        uint32_t sa = s0 + s * STAGEB;
        uint32_t sb = sa + A_BYTES;
        int ktA = c * BK;
        size_t ktB = (size_t)c * BK * N;
#pragma unroll
        for (int it = 0; it < 2; it++) CP16(sa + adst[it], aptr[it] + ktA);
#pragma unroll
        for (int it = 0; it < 4; it++) CP16(sb + bdst[it], bptr[it] + ktB);
        CP_COMMIT();
    };

#pragma unroll
    for (int p = 0; p < NSTAGE - 1; p++)
        if (p < nch) load_stage(p, p);

    // ldmatrix per-thread offsets
    int a_row = lane & 15, a_k = (lane >> 4) * 8;
    int b_k = (lane & 7) + ((lane >> 3) & 1) * 8;
    int b_n = (lane >> 4) * 8;

    uint32_t af[2][4][4], bf[2][8][2];

    for (int c = 0; c < nch; c++) {
        int s = c % NSTAGE;
        int pend = nch - 1 - c;
        if (pend >= 4)      asm volatile("cp.async.wait_group 4;" ::: "memory");
        else if (pend == 3) asm volatile("cp.async.wait_group 3;" ::: "memory");
        else if (pend == 2) asm volatile("cp.async.wait_group 2;" ::: "memory");
        else if (pend == 1) asm volatile("cp.async.wait_group 1;" ::: "memory");
        else                asm volatile("cp.async.wait_group 0;" ::: "memory");
        __syncthreads();
        if (c + NSTAGE - 1 < nch) load_stage(c + NSTAGE - 1, (c + NSTAGE - 1) % NSTAGE);

        uint32_t sa = s0 + s * STAGEB;
        uint32_t sb = sa + A_BYTES;

#pragma unroll
        for (int ks = 0; ks < 2; ks++) {
            int k0 = ks * 16;
#pragma unroll
            for (int mf = 0; mf < 4; mf++)
                ldsm4(af[ks][mf], sa + ((wm * 64 + mf * 16 + a_row) * ASTR + k0 + a_k) * 2);
#pragma unroll
            for (int p = 0; p < 4; p++) {
                uint32_t r[4];
                ldsm4t(r, sb + ((k0 + b_k) * BSTR + wn * 64 + p * 16 + b_n) * 2);
                bf[ks][2 * p][0] = r[0]; bf[ks][2 * p][1] = r[1];
                bf[ks][2 * p + 1][0] = r[2]; bf[ks][2 * p + 1][1] = r[3];
            }
        }
#pragma unroll
        for (int ks = 0; ks < 2; ks++)
#pragma unroll
            for (int mf = 0; mf < 4; mf++)
#pragma unroll
                for (int nf = 0; nf < 8; nf++)
                    mma_f16(acc[mf][nf], af[ks][mf], bf[ks][nf]);
    }

    // epilogue
    int gq = lane >> 2, tc4 = lane & 3;
#pragma unroll
    for (int mf = 0; mf < 4; mf++) {
        int rA = row0 + wm * 64 + mf * 16 + gq;
        int rB = rA + 8;
        bool vA = rA < cnt, vB = rB < cnt;
        size_t cra = EXPERT ? (size_t)(base + rA) : (size_t)rA;
        size_t crb = EXPERT ? (size_t)(base + rB) : (size_t)rB;
#pragma unroll
        for (int nf = 0; nf < 8; nf++) {
            int col = n0 + wn * 64 + nf * 8 + tc4 * 2;
            if (EPI == EPI_F) {
                float* C = (float*)Cv;
                if (vA) *(float2*)(C + cra * (size_t)Cw + col) = make_float2(acc[mf][nf][0], acc[mf][nf][1]);
                if (vB) *(float2*)(C + crb * (size_t)Cw + col) = make_float2(acc[mf][nf][2], acc[mf][nf][3]);
            } else if (EPI == EPI_H) {
                __half* C = (__half*)Cv;
                if (vA) *(__half2*)(C + cra * (size_t)Cw + col) = __floats2half2_rn(acc[mf][nf][0], acc[mf][nf][1]);
                if (vB) *(__half2*)(C + crb * (size_t)Cw + col) = __floats2half2_rn(acc[mf][nf][2], acc[mf][nf][3]);
            } else {  // EPI_SP: (gate,up) pair -> silu(g)*u
                __half* C = (__half*)Cv;
                int lcol = col >> 1;
                if (vA) C[cra * (size_t)Cw + lcol] = __float2half_rn(silu_mul(acc[mf][nf][0], acc[mf][nf][1]));
                if (vB) C[crb * (size_t)Cw + lcol] = __float2half_rn(silu_mul(acc[mf][nf][2], acc[mf][nf][3]));
            }
        }
    }
}

// ---------------- launch ----------------
extern "C" void kernel_launch(void* const* d_in, const int* in_sizes, int n_in,
                              void* d_out, int out_size) {
    const float* x   = (const float*)d_in[0];
    const float* gw  = (const float*)d_in[1];
    const float* wg  = (const float*)d_in[2];
    const float* wu  = (const float*)d_in[3];
    const float* wd  = (const float*)d_in[4];
    const float* swg = (const float*)d_in[5];
    const float* swu = (const float*)d_in[6];
    const float* swd = (const float*)d_in[7];
    float* out = (float*)d_out;

    __half *p_xh, *p_wguh, *p_wdh, *p_swguh, *p_swdh, *p_hr, *p_hs, *p_dout;
    cudaGetSymbolAddress((void**)&p_xh, g_xh);
    cudaGetSymbolAddress((void**)&p_wguh, g_wguh);
    cudaGetSymbolAddress((void**)&p_wdh, g_wdh);
    cudaGetSymbolAddress((void**)&p_swguh, g_swguh);
    cudaGetSymbolAddress((void**)&p_swdh, g_swdh);
    cudaGetSymbolAddress((void**)&p_hr, g_hr);
    cudaGetSymbolAddress((void**)&p_hs, g_hs);
    cudaGetSymbolAddress((void**)&p_dout, g_dout);

    cudaFuncSetAttribute(hgemm<false, false, EPI_SP>, cudaFuncAttributeMaxDynamicSharedMemorySize, SMEM_BYTES);
    cudaFuncSetAttribute(hgemm<false, false, EPI_F>,  cudaFuncAttributeMaxDynamicSharedMemorySize, SMEM_BYTES);
    cudaFuncSetAttribute(hgemm<true, true, EPI_SP>,   cudaFuncAttributeMaxDynamicSharedMemorySize, SMEM_BYTES);
    cudaFuncSetAttribute(hgemm<true, false, EPI_H>,   cudaFuncAttributeMaxDynamicSharedMemorySize, SMEM_BYTES);

    dim3 blk(256);
    dim3 gblk(NTHR);

    const size_t nW = (size_t)N_EXP * H_DIM * M_DIM;   // 92.3M
    const size_t nS = (size_t)H_DIM * SH_DIM;          // 5.77M

    // shared path first (puts a GEMM in the ncu capture window)
    cvt_f2h<<<(T_TOK * H_DIM) / 4096, blk>>>(x, p_xh);                 // 0
    cvt_interleave<<<(int)(nS / 4096), blk>>>(swg, swu, p_swguh);      // 1
    cvt_f2h<<<(int)(nS / 4096), blk>>>(swd, p_swdh);                   // 2
    hgemm<false, false, EPI_SP><<<dim3(2 * SH_DIM / BN, T_TOK / BM, 1), gblk, SMEM_BYTES>>>(
        p_xh, p_swguh, p_hs, T_TOK, 2 * SH_DIM, H_DIM);                // 3
    hgemm<false, false, EPI_F><<<dim3(H_DIM / BN, T_TOK / BM, 1), gblk, SMEM_BYTES>>>(
        p_hs, p_swdh, out, T_TOK, H_DIM, SH_DIM);                      // 4

    // routed-path converts + routing
    cvt_interleave<<<(int)(nW / 4096), blk>>>(wg, wu, p_wguh);         // 5
    cvt_f2h<<<(int)(nW / 4096), blk>>>(wd, p_wdh);                     // 6
    reset_kernel<<<1, 64>>>();
    gate_kernel<<<(T_TOK * 32) / 256, blk>>>(x, gw);
    route_kernel<<<T_TOK / 256, blk>>>();
    scan_kernel<<<1, 32>>>();
    scatter_kernel<<<TK / 256, blk>>>();

    // routed experts: fused gate|up -> hr, down -> dout (fp16)
    hgemm<true, true, EPI_SP><<<dim3(2 * M_DIM / BN, T_TOK / BM, N_EXP), gblk, SMEM_BYTES>>>(
        p_xh, p_wguh, p_hr, TK, 2 * M_DIM, H_DIM);
    hgemm<true, false, EPI_H><<<dim3(H_DIM / BN, T_TOK / BM, N_EXP), gblk, SMEM_BYTES>>>(
        p_hr, p_wdh, p_dout, TK, H_DIM, M_DIM);

    // weighted combine of routed outputs into out
    combine_kernel<<<T_TOK, blk>>>(out);
}

// round 8
// speedup vs baseline: 1.1343x; 1.1343x over previous
#include <cuda_runtime.h>
#include <cuda_fp16.h>
#include <math.h>
#include <cstdint>

// ---------------- problem constants ----------------
#define T_TOK   8192
#define H_DIM   2048
#define N_EXP   32
#define TOPK    6
#define M_DIM   1408
#define SH_DIM  2816
#define TK      (T_TOK * TOPK)   // 49152

// ---------------- scratch (device globals) ----------------
__device__ __half g_xh[(size_t)T_TOK * H_DIM];            // fp16 x
__device__ __half g_wguh[(size_t)N_EXP * H_DIM * 2 * M_DIM];  // interleaved gate|up weights
__device__ __half g_wdh[(size_t)N_EXP * M_DIM * H_DIM];
__device__ __half g_swguh[(size_t)H_DIM * 2 * SH_DIM];    // interleaved shared gate|up
__device__ __half g_swdh[(size_t)SH_DIM * H_DIM];
__device__ __half g_hr[(size_t)TK * M_DIM];               // routed silu(g)*u
__device__ __half g_dout[(size_t)TK * H_DIM];             // routed down out (fp16)
__device__ __half g_hs[(size_t)T_TOK * SH_DIM];           // shared silu(g)*u
__device__ float  g_scores[T_TOK * N_EXP];
__device__ int    g_sel[TK];
__device__ float  g_selw[TK];
__device__ int    g_counts[N_EXP];
__device__ int    g_offsets[N_EXP + 1];
__device__ int    g_fill[N_EXP];
__device__ int    g_toklist[TK];
__device__ int    g_pos[TK];

// ---------------- PTX helpers ----------------
__device__ __forceinline__ uint32_t smem_u32(const void* p) {
    uint32_t a;
    asm("{ .reg .u64 t; cvta.to.shared.u64 t, %1; cvt.u32.u64 %0, t; }" : "=r"(a) : "l"(p));
    return a;
}
#define CP16(dst, src)  asm volatile("cp.async.cg.shared.global [%0], [%1], 16;" :: "r"(dst), "l"(src) : "memory")
#define CP_COMMIT()     asm volatile("cp.async.commit_group;" ::: "memory")

__device__ __forceinline__ void ldsm4(uint32_t* r, uint32_t addr) {
    asm volatile("ldmatrix.sync.aligned.m8n8.x4.shared.b16 {%0,%1,%2,%3}, [%4];"
                 : "=r"(r[0]), "=r"(r[1]), "=r"(r[2]), "=r"(r[3]) : "r"(addr));
}
__device__ __forceinline__ void ldsm4t(uint32_t* r, uint32_t addr) {
    asm volatile("ldmatrix.sync.aligned.m8n8.x4.trans.shared.b16 {%0,%1,%2,%3}, [%4];"
                 : "=r"(r[0]), "=r"(r[1]), "=r"(r[2]), "=r"(r[3]) : "r"(addr));
}
__device__ __forceinline__ void mma_f16(float* d, const uint32_t* a, const uint32_t* b) {
    asm volatile("mma.sync.aligned.m16n8k16.row.col.f32.f16.f16.f32 "
                 "{%0,%1,%2,%3}, {%4,%5,%6,%7}, {%8,%9}, {%0,%1,%2,%3};"
                 : "+f"(d[0]), "+f"(d[1]), "+f"(d[2]), "+f"(d[3])
                 : "r"(a[0]), "r"(a[1]), "r"(a[2]), "r"(a[3]), "r"(b[0]), "r"(b[1]));
}
__device__ __forceinline__ float silu_mul(float g, float u) {
    return g / (1.f + expf(-g)) * u;
}

// ---------------- small kernels ----------------
__global__ void reset_kernel() {
    int i = threadIdx.x;
    if (i < N_EXP) { g_counts[i] = 0; g_fill[i] = 0; }
}

// fp32 -> fp16, 16 elems/thread (n divisible by 4096)
__global__ void cvt_f2h(const float* __restrict__ in, __half* __restrict__ out) {
    size_t i = ((size_t)blockIdx.x * blockDim.x + threadIdx.x) * 16;
    float4 v0 = *(const float4*)(in + i);
    float4 v1 = *(const float4*)(in + i + 4);
    float4 v2 = *(const float4*)(in + i + 8);
    float4 v3 = *(const float4*)(in + i + 12);
    __half2 h[8];
    h[0] = __floats2half2_rn(v0.x, v0.y); h[1] = __floats2half2_rn(v0.z, v0.w);
    h[2] = __floats2half2_rn(v1.x, v1.y); h[3] = __floats2half2_rn(v1.z, v1.w);
    h[4] = __floats2half2_rn(v2.x, v2.y); h[5] = __floats2half2_rn(v2.z, v2.w);
    h[6] = __floats2half2_rn(v3.x, v3.y); h[7] = __floats2half2_rn(v3.z, v3.w);
    *(uint4*)(out + i)     = *(uint4*)h;
    *(uint4*)(out + i + 8) = *(uint4*)(h + 4);
}

// interleave: out[2i]=a[i], out[2i+1]=b[i] as fp16, 16 inputs/thread
__global__ void cvt_interleave(const float* __restrict__ a, const float* __restrict__ b,
                               __half* __restrict__ out) {
    size_t i = ((size_t)blockIdx.x * blockDim.x + threadIdx.x) * 16;
    float4 a0 = *(const float4*)(a + i),     a1 = *(const float4*)(a + i + 4);
    float4 a2 = *(const float4*)(a + i + 8), a3 = *(const float4*)(a + i + 12);
    float4 b0 = *(const float4*)(b + i),     b1 = *(const float4*)(b + i + 4);
    float4 b2 = *(const float4*)(b + i + 8), b3 = *(const float4*)(b + i + 12);
    __half2 h[16];
    h[0]  = __floats2half2_rn(a0.x, b0.x); h[1]  = __floats2half2_rn(a0.y, b0.y);
    h[2]  = __floats2half2_rn(a0.z, b0.z); h[3]  = __floats2half2_rn(a0.w, b0.w);
    h[4]  = __floats2half2_rn(a1.x, b1.x); h[5]  = __floats2half2_rn(a1.y, b1.y);
    h[6]  = __floats2half2_rn(a1.z, b1.z); h[7]  = __floats2half2_rn(a1.w, b1.w);
    h[8]  = __floats2half2_rn(a2.x, b2.x); h[9]  = __floats2half2_rn(a2.y, b2.y);
    h[10] = __floats2half2_rn(a2.z, b2.z); h[11] = __floats2half2_rn(a2.w, b2.w);
    h[12] = __floats2half2_rn(a3.x, b3.x); h[13] = __floats2half2_rn(a3.y, b3.y);
    h[14] = __floats2half2_rn(a3.z, b3.z); h[15] = __floats2half2_rn(a3.w, b3.w);
    *(uint4*)(out + 2 * i)      = *(uint4*)(h);
    *(uint4*)(out + 2 * i + 8)  = *(uint4*)(h + 4);
    *(uint4*)(out + 2 * i + 16) = *(uint4*)(h + 8);
    *(uint4*)(out + 2 * i + 24) = *(uint4*)(h + 12);
}

__global__ void gate_kernel(const float* __restrict__ x, const float* __restrict__ gw) {
    int warp = (blockIdx.x * blockDim.x + threadIdx.x) >> 5;
    int lane = threadIdx.x & 31;
    if (warp >= T_TOK) return;
    const float* xr = x + (size_t)warp * H_DIM;
    float acc = 0.f;
#pragma unroll 4
    for (int h = 0; h < H_DIM; h += 4) {
        float4 xv = *(const float4*)(xr + h);
        acc += xv.x * gw[(h + 0) * N_EXP + lane];
        acc += xv.y * gw[(h + 1) * N_EXP + lane];
        acc += xv.z * gw[(h + 2) * N_EXP + lane];
        acc += xv.w * gw[(h + 3) * N_EXP + lane];
    }
    g_scores[warp * N_EXP + lane] = 1.f / (1.f + expf(-acc));
}

__global__ void route_kernel() {
    int t = blockIdx.x * blockDim.x + threadIdx.x;
    if (t >= T_TOK) return;
    float sc[N_EXP];
#pragma unroll
    for (int e = 0; e < N_EXP; e++) sc[e] = g_scores[t * N_EXP + e];
    float gm[4];
#pragma unroll
    for (int g = 0; g < 4; g++) {
        float m = sc[g * 8];
#pragma unroll
        for (int j = 1; j < 8; j++) m = fmaxf(m, sc[g * 8 + j]);
        gm[g] = m;
    }
    int g1 = 0;
#pragma unroll
    for (int g = 1; g < 4; g++) if (gm[g] > gm[g1]) g1 = g;
    int g2 = (g1 == 0) ? 1 : 0;
#pragma unroll
    for (int g = 0; g < 4; g++) if (g != g1 && gm[g] > gm[g2]) g2 = g;
    unsigned allowed = 0;
#pragma unroll
    for (int e = 0; e < N_EXP; e++) {
        int g = e >> 3;
        if (g == g1 || g == g2) allowed |= (1u << e);
    }
    unsigned picked = 0;
    float wsum = 0.f;
    int etmp[TOPK]; float wtmp[TOPK];
#pragma unroll
    for (int k = 0; k < TOPK; k++) {
        int best = -1; float bv = -1.f;
#pragma unroll
        for (int e = 0; e < N_EXP; e++) {
            if (!((allowed >> e) & 1u)) continue;
            if ((picked >> e) & 1u) continue;
            if (sc[e] > bv) { bv = sc[e]; best = e; }
        }
        picked |= (1u << best);
        etmp[k] = best; wtmp[k] = bv; wsum += bv;
    }
    float inv = 1.f / wsum;
#pragma unroll
    for (int k = 0; k < TOPK; k++) {
        g_sel[t * TOPK + k]  = etmp[k];
        g_selw[t * TOPK + k] = wtmp[k] * inv;
        atomicAdd(&g_counts[etmp[k]], 1);
    }
}

__global__ void scan_kernel() {
    if (threadIdx.x == 0) {
        int s = 0;
        for (int e = 0; e < N_EXP; e++) { g_offsets[e] = s; s += g_counts[e]; }
        g_offsets[N_EXP] = s;
    }
}

__global__ void scatter_kernel() {
    int i = blockIdx.x * blockDim.x + threadIdx.x;
    if (i >= TK) return;
    int e = g_sel[i];
    int p = g_offsets[e] + atomicAdd(&g_fill[e], 1);
    g_toklist[p] = i / TOPK;
    g_pos[i] = p;
}

// combine: out[t] += sum_k w_k * dout_fp16[pos_k]
__global__ void combine_kernel(float* __restrict__ out) {
    int t = blockIdx.x;
    float w[TOPK]; int ps[TOPK];
#pragma unroll
    for (int k = 0; k < TOPK; k++) { w[k] = g_selw[t * TOPK + k]; ps[k] = g_pos[t * TOPK + k]; }
    for (int h2 = threadIdx.x; h2 < H_DIM / 2; h2 += blockDim.x) {
        float2 acc = *(float2*)(out + (size_t)t * H_DIM + h2 * 2);
#pragma unroll
        for (int k = 0; k < TOPK; k++) {
            float2 v = __half22float2(*(const __half2*)(g_dout + (size_t)ps[k] * H_DIM + h2 * 2));
            acc.x += w[k] * v.x; acc.y += w[k] * v.y;
        }
        *(float2*)(out + (size_t)t * H_DIM + h2 * 2) = acc;
    }
}

// ---------------- FP16 mma.sync GEMM ----------------
// C[row][n] = sum_k A[arow][k] * B[k][n]
// Tile 128x128x64, 4 warps (2x2 grid, 64x64 warp tiles),
// 2-stage double buffer (one sync per 64-K), 2 CTAs/SM.
#define BM 128
#define BN 128
#define BK 64
#define NTHR 128
#define ASTR 72      // halves per A smem row (128B data + 16B pad)
#define BSTR 136     // halves per B smem row (256B data + 16B pad)
#define A_BYTES (BM * ASTR * 2)          // 18432
#define B_BYTES (BK * BSTR * 2)          // 17408
#define STAGEB  (A_BYTES + B_BYTES)      // 35840
#define SMEM_BYTES (2 * STAGEB)          // 71680

#define EPI_F  0
#define EPI_H  1
#define EPI_SP 2

template <bool EXPERT, bool GATHER, int EPI>
__global__ void __launch_bounds__(NTHR)
hgemm(const __half* __restrict__ A, const __half* __restrict__ B0,
      void* __restrict__ Cv, int rowsTotal, int N, int K) {
    int e = EXPERT ? blockIdx.z : 0;
    int base = 0, cnt;
    if (EXPERT) { base = g_offsets[e]; cnt = g_offsets[e + 1] - base; }
    else        cnt = rowsTotal;
    int row0 = blockIdx.y * BM;
    if (row0 >= cnt) return;
    int n0 = blockIdx.x * BN;
    const __half* B = EXPERT ? B0 + (size_t)e * K * N : B0;
    const int Cw = (EPI == EPI_SP) ? (N >> 1) : N;

    extern __shared__ char smem[];
    uint32_t s0 = smem_u32(smem);

    int tid = threadIdx.x, wid = tid >> 5, lane = tid & 31;
    int wm = wid >> 1, wn = wid & 1;     // 2x2 warp grid, 64x64 warp tile

    // ---- loader mapping ----
    // A: 128 rows x 8 16B-chunks = 1024, 8 per thread: row = tid>>3 + it*16, ch = tid&7
    // B: 64 rows x 8 16B-chunks... (64 rows x 16 chunks = 1024), krow = tid>>4 + it*8, ch = tid&15
    int a_ch = tid & 7;
    int a_row_base = tid >> 3;           // + it*16
    const __half* aptr[8];
#pragma unroll
    for (int it = 0; it < 8; it++) {
        int row = a_row_base + it * 16;
        int r = min(row0 + row, cnt - 1);
        int arow = GATHER ? g_toklist[base + r] : (base + r);
        aptr[it] = A + (size_t)arow * K + a_ch * 8;
    }
    uint32_t adst0 = (uint32_t)(a_row_base * ASTR + a_ch * 8) * 2;   // + it*16*ASTR*2
    int b_ch = tid & 15;
    int b_krow_base = tid >> 4;          // + it*8
    const __half* bptr0 = B + (size_t)b_krow_base * N + n0 + b_ch * 8;
    uint32_t bdst0 = (uint32_t)(b_krow_base * BSTR + b_ch * 8) * 2;  // + it*8*BSTR*2

    float acc[4][8][4];
#pragma unroll
    for (int mf = 0; mf < 4; mf++)
#pragma unroll
        for (int nf = 0; nf < 8; nf++)
#pragma unroll
            for (int q = 0; q < 4; q++) acc[mf][nf][q] = 0.f;

    const int nch = K / BK;

    auto load_stage = [&](int c, int s) {
        uint32_t sa = s0 + s * STAGEB;
        uint32_t sb = sa + A_BYTES;
        int ktA = c * BK;
        size_t ktB = (size_t)c * BK * N;
#pragma unroll
        for (int it = 0; it < 8; it++)
            CP16(sa + adst0 + it * (16 * ASTR * 2), aptr[it] + ktA);
#pragma unroll
        for (int it = 0; it < 8; it++)
            CP16(sb + bdst0 + it * (8 * BSTR * 2), bptr0 + ktB + (size_t)it * 8 * N);
        CP_COMMIT();
    };

    load_stage(0, 0);

    // ldmatrix per-thread offsets
    int a_row = lane & 15, a_k = (lane >> 4) * 8;
    int b_k = (lane & 7) + ((lane >> 3) & 1) * 8;
    int b_n = (lane >> 4) * 8;

    uint32_t af[2][4][4], bf[2][8][2];

    for (int c = 0; c < nch; c++) {
        int s = c & 1;
        asm volatile("cp.async.wait_group 0;" ::: "memory");
        __syncthreads();
        if (c + 1 < nch) load_stage(c + 1, s ^ 1);

        uint32_t sa = s0 + s * STAGEB;
        uint32_t sb = sa + A_BYTES;

#pragma unroll
        for (int half = 0; half < 2; half++) {
            int kb = half * 32;
#pragma unroll
            for (int ks = 0; ks < 2; ks++) {
                int k0 = kb + ks * 16;
#pragma unroll
                for (int mf = 0; mf < 4; mf++)
                    ldsm4(af[ks][mf], sa + ((wm * 64 + mf * 16 + a_row) * ASTR + k0 + a_k) * 2);
#pragma unroll
                for (int p = 0; p < 4; p++) {
                    uint32_t r[4];
                    ldsm4t(r, sb + ((k0 + b_k) * BSTR + wn * 64 + p * 16 + b_n) * 2);
                    bf[ks][2 * p][0] = r[0]; bf[ks][2 * p][1] = r[1];
                    bf[ks][2 * p + 1][0] = r[2]; bf[ks][2 * p + 1][1] = r[3];
                }
            }
#pragma unroll
            for (int ks = 0; ks < 2; ks++)
#pragma unroll
                for (int mf = 0; mf < 4; mf++)
#pragma unroll
                    for (int nf = 0; nf < 8; nf++)
                        mma_f16(acc[mf][nf], af[ks][mf], bf[ks][nf]);
        }
    }

    // epilogue
    int gq = lane >> 2, tc4 = lane & 3;
#pragma unroll
    for (int mf = 0; mf < 4; mf++) {
        int rA = row0 + wm * 64 + mf * 16 + gq;
        int rB = rA + 8;
        bool vA = rA < cnt, vB = rB < cnt;
        size_t cra = EXPERT ? (size_t)(base + rA) : (size_t)rA;
        size_t crb = EXPERT ? (size_t)(base + rB) : (size_t)rB;
#pragma unroll
        for (int nf = 0; nf < 8; nf++) {
            int col = n0 + wn * 64 + nf * 8 + tc4 * 2;
            if (EPI == EPI_F) {
                float* C = (float*)Cv;
                if (vA) *(float2*)(C + cra * (size_t)Cw + col) = make_float2(acc[mf][nf][0], acc[mf][nf][1]);
                if (vB) *(float2*)(C + crb * (size_t)Cw + col) = make_float2(acc[mf][nf][2], acc[mf][nf][3]);
            } else if (EPI == EPI_H) {
                __half* C = (__half*)Cv;
                if (vA) *(__half2*)(C + cra * (size_t)Cw + col) = __floats2half2_rn(acc[mf][nf][0], acc[mf][nf][1]);
                if (vB) *(__half2*)(C + crb * (size_t)Cw + col) = __floats2half2_rn(acc[mf][nf][2], acc[mf][nf][3]);
            } else {  // EPI_SP: (gate,up) pair -> silu(g)*u
                __half* C = (__half*)Cv;
                int lcol = col >> 1;
                if (vA) C[cra * (size_t)Cw + lcol] = __float2half_rn(silu_mul(acc[mf][nf][0], acc[mf][nf][1]));
                if (vB) C[crb * (size_t)Cw + lcol] = __float2half_rn(silu_mul(acc[mf][nf][2], acc[mf][nf][3]));
            }
        }
    }
}

// ---------------- launch ----------------
extern "C" void kernel_launch(void* const* d_in, const int* in_sizes, int n_in,
                              void* d_out, int out_size) {
    const float* x   = (const float*)d_in[0];
    const float* gw  = (const float*)d_in[1];
    const float* wg  = (const float*)d_in[2];
    const float* wu  = (const float*)d_in[3];
    const float* wd  = (const float*)d_in[4];
    const float* swg = (const float*)d_in[5];
    const float* swu = (const float*)d_in[6];
    const float* swd = (const float*)d_in[7];
    float* out = (float*)d_out;

    __half *p_xh, *p_wguh, *p_wdh, *p_swguh, *p_swdh, *p_hr, *p_hs, *p_dout;
    cudaGetSymbolAddress((void**)&p_xh, g_xh);
    cudaGetSymbolAddress((void**)&p_wguh, g_wguh);
    cudaGetSymbolAddress((void**)&p_wdh, g_wdh);
    cudaGetSymbolAddress((void**)&p_swguh, g_swguh);
    cudaGetSymbolAddress((void**)&p_swdh, g_swdh);
    cudaGetSymbolAddress((void**)&p_hr, g_hr);
    cudaGetSymbolAddress((void**)&p_hs, g_hs);
    cudaGetSymbolAddress((void**)&p_dout, g_dout);

    cudaFuncSetAttribute(hgemm<false, false, EPI_SP>, cudaFuncAttributeMaxDynamicSharedMemorySize, SMEM_BYTES);
    cudaFuncSetAttribute(hgemm<false, false, EPI_F>,  cudaFuncAttributeMaxDynamicSharedMemorySize, SMEM_BYTES);
    cudaFuncSetAttribute(hgemm<true, true, EPI_SP>,   cudaFuncAttributeMaxDynamicSharedMemorySize, SMEM_BYTES);
    cudaFuncSetAttribute(hgemm<true, false, EPI_H>,   cudaFuncAttributeMaxDynamicSharedMemorySize, SMEM_BYTES);

    dim3 blk(256);
    dim3 gblk(NTHR);

    const size_t nW = (size_t)N_EXP * H_DIM * M_DIM;   // 92.3M
    const size_t nS = (size_t)H_DIM * SH_DIM;          // 5.77M

    // shared path first (keeps a GEMM in the ncu capture window at index 3)
    cvt_f2h<<<(T_TOK * H_DIM) / 4096, blk>>>(x, p_xh);                 // 0
    cvt_interleave<<<(int)(nS / 4096), blk>>>(swg, swu, p_swguh);      // 1
    cvt_f2h<<<(int)(nS / 4096), blk>>>(swd, p_swdh);                   // 2
    hgemm<false, false, EPI_SP><<<dim3(2 * SH_DIM / BN, T_TOK / BM, 1), gblk, SMEM_BYTES>>>(
        p_xh, p_swguh, p_hs, T_TOK, 2 * SH_DIM, H_DIM);                // 3
    hgemm<false, false, EPI_F><<<dim3(H_DIM / BN, T_TOK / BM, 1), gblk, SMEM_BYTES>>>(
        p_hs, p_swdh, out, T_TOK, H_DIM, SH_DIM);                      // 4

    // routed-path converts + routing
    cvt_interleave<<<(int)(nW / 4096), blk>>>(wg, wu, p_wguh);
    cvt_f2h<<<(int)(nW / 4096), blk>>>(wd, p_wdh);
    reset_kernel<<<1, 64>>>();
    gate_kernel<<<(T_TOK * 32) / 256, blk>>>(x, gw);
    route_kernel<<<T_TOK / 256, blk>>>();
    scan_kernel<<<1, 32>>>();
    scatter_kernel<<<TK / 256, blk>>>();

    // routed experts: fused gate|up -> hr, down -> dout (fp16)
    hgemm<true, true, EPI_SP><<<dim3(2 * M_DIM / BN, T_TOK / BM, N_EXP), gblk, SMEM_BYTES>>>(
        p_xh, p_wguh, p_hr, TK, 2 * M_DIM, H_DIM);
    hgemm<true, false, EPI_H><<<dim3(H_DIM / BN, T_TOK / BM, N_EXP), gblk, SMEM_BYTES>>>(
        p_hr, p_wdh, p_dout, TK, H_DIM, M_DIM);

    // weighted combine of routed outputs into out
    combine_kernel<<<T_TOK, blk>>>(out);
}

// round 9
// speedup vs baseline: 1.2991x; 1.1453x over previous
#include <cuda_runtime.h>
#include <cuda_fp16.h>
#include <math.h>
#include <cstdint>

// ---------------- problem constants ----------------
#define T_TOK   8192
#define H_DIM   2048
#define N_EXP   32
#define TOPK    6
#define M_DIM   1408
#define SH_DIM  2816
#define TK      (T_TOK * TOPK)   // 49152

// ---------------- scratch (device globals) ----------------
__device__ __half g_xh[(size_t)T_TOK * H_DIM];            // fp16 x
__device__ __half g_wguh[(size_t)N_EXP * H_DIM * 2 * M_DIM];  // interleaved gate|up weights
__device__ __half g_wdh[(size_t)N_EXP * M_DIM * H_DIM];
__device__ __half g_swguh[(size_t)H_DIM * 2 * SH_DIM];    // interleaved shared gate|up
__device__ __half g_swdh[(size_t)SH_DIM * H_DIM];
__device__ __half g_hr[(size_t)TK * M_DIM];               // routed silu(g)*u
__device__ __half g_dout[(size_t)TK * H_DIM];             // routed down out (fp16)
__device__ __half g_hs[(size_t)T_TOK * SH_DIM];           // shared silu(g)*u
__device__ float  g_scores[T_TOK * N_EXP];
__device__ int    g_sel[TK];
__device__ float  g_selw[TK];
__device__ int    g_counts[N_EXP];
__device__ int    g_offsets[N_EXP + 1];
__device__ int    g_fill[N_EXP];
__device__ int    g_toklist[TK];
__device__ int    g_pos[TK];

// ---------------- PTX helpers ----------------
__device__ __forceinline__ uint32_t smem_u32(const void* p) {
    uint32_t a;
    asm("{ .reg .u64 t; cvta.to.shared.u64 t, %1; cvt.u32.u64 %0, t; }" : "=r"(a) : "l"(p));
    return a;
}
#define CP16(dst, src)  asm volatile("cp.async.cg.shared.global [%0], [%1], 16;" :: "r"(dst), "l"(src) : "memory")
#define CP_COMMIT()     asm volatile("cp.async.commit_group;" ::: "memory")

__device__ __forceinline__ void ldsm4(uint32_t* r, uint32_t addr) {
    asm volatile("ldmatrix.sync.aligned.m8n8.x4.shared.b16 {%0,%1,%2,%3}, [%4];"
                 : "=r"(r[0]), "=r"(r[1]), "=r"(r[2]), "=r"(r[3]) : "r"(addr));
}
__device__ __forceinline__ void ldsm4t(uint32_t* r, uint32_t addr) {
    asm volatile("ldmatrix.sync.aligned.m8n8.x4.trans.shared.b16 {%0,%1,%2,%3}, [%4];"
                 : "=r"(r[0]), "=r"(r[1]), "=r"(r[2]), "=r"(r[3]) : "r"(addr));
}
__device__ __forceinline__ void mma_f16(float* d, const uint32_t* a, const uint32_t* b) {
    asm volatile("mma.sync.aligned.m16n8k16.row.col.f32.f16.f16.f32 "
                 "{%0,%1,%2,%3}, {%4,%5,%6,%7}, {%8,%9}, {%0,%1,%2,%3};"
                 : "+f"(d[0]), "+f"(d[1]), "+f"(d[2]), "+f"(d[3])
                 : "r"(a[0]), "r"(a[1]), "r"(a[2]), "r"(a[3]), "r"(b[0]), "r"(b[1]));
}
__device__ __forceinline__ float silu_mul(float g, float u) {
    return g / (1.f + expf(-g)) * u;
}

// ---------------- small kernels ----------------
__global__ void reset_kernel() {
    int i = threadIdx.x;
    if (i < N_EXP) { g_counts[i] = 0; g_fill[i] = 0; }
}

// fp32 -> fp16, 4 elems/thread (n divisible by 1024): 1 LDG.128 + 1 STG.64
__global__ void cvt_f2h(const float* __restrict__ in, __half* __restrict__ out) {
    size_t i = ((size_t)blockIdx.x * blockDim.x + threadIdx.x) * 4;
    float4 v = *(const float4*)(in + i);
    __half2 h[2];
    h[0] = __floats2half2_rn(v.x, v.y);
    h[1] = __floats2half2_rn(v.z, v.w);
    *(uint2*)(out + i) = *(uint2*)h;
}

// interleave: out[2i]=a[i], out[2i+1]=b[i] as fp16, 4 inputs/thread: 2 LDG.128 + 1 STG.128
__global__ void cvt_interleave(const float* __restrict__ a, const float* __restrict__ b,
                               __half* __restrict__ out) {
    size_t i = ((size_t)blockIdx.x * blockDim.x + threadIdx.x) * 4;
    float4 av = *(const float4*)(a + i);
    float4 bv = *(const float4*)(b + i);
    __half2 h[4];
    h[0] = __floats2half2_rn(av.x, bv.x); h[1] = __floats2half2_rn(av.y, bv.y);
    h[2] = __floats2half2_rn(av.z, bv.z); h[3] = __floats2half2_rn(av.w, bv.w);
    *(uint4*)(out + 2 * i) = *(uint4*)h;
}

__global__ void gate_kernel(const float* __restrict__ x, const float* __restrict__ gw) {
    int warp = (blockIdx.x * blockDim.x + threadIdx.x) >> 5;
    int lane = threadIdx.x & 31;
    if (warp >= T_TOK) return;
    const float* xr = x + (size_t)warp * H_DIM;
    float acc = 0.f;
#pragma unroll 4
    for (int h = 0; h < H_DIM; h += 4) {
        float4 xv = *(const float4*)(xr + h);
        acc += xv.x * gw[(h + 0) * N_EXP + lane];
        acc += xv.y * gw[(h + 1) * N_EXP + lane];
        acc += xv.z * gw[(h + 2) * N_EXP + lane];
        acc += xv.w * gw[(h + 3) * N_EXP + lane];
    }
    g_scores[warp * N_EXP + lane] = 1.f / (1.f + expf(-acc));
}

__global__ void route_kernel() {
    int t = blockIdx.x * blockDim.x + threadIdx.x;
    if (t >= T_TOK) return;
    float sc[N_EXP];
#pragma unroll
    for (int e = 0; e < N_EXP; e++) sc[e] = g_scores[t * N_EXP + e];
    float gm[4];
#pragma unroll
    for (int g = 0; g < 4; g++) {
        float m = sc[g * 8];
#pragma unroll
        for (int j = 1; j < 8; j++) m = fmaxf(m, sc[g * 8 + j]);
        gm[g] = m;
    }
    int g1 = 0;
#pragma unroll
    for (int g = 1; g < 4; g++) if (gm[g] > gm[g1]) g1 = g;
    int g2 = (g1 == 0) ? 1 : 0;
#pragma unroll
    for (int g = 0; g < 4; g++) if (g != g1 && gm[g] > gm[g2]) g2 = g;
    unsigned allowed = 0;
#pragma unroll
    for (int e = 0; e < N_EXP; e++) {
        int g = e >> 3;
        if (g == g1 || g == g2) allowed |= (1u << e);
    }
    unsigned picked = 0;
    float wsum = 0.f;
    int etmp[TOPK]; float wtmp[TOPK];
#pragma unroll
    for (int k = 0; k < TOPK; k++) {
        int best = -1; float bv = -1.f;
#pragma unroll
        for (int e = 0; e < N_EXP; e++) {
            if (!((allowed >> e) & 1u)) continue;
            if ((picked >> e) & 1u) continue;
            if (sc[e] > bv) { bv = sc[e]; best = e; }
        }
        picked |= (1u << best);
        etmp[k] = best; wtmp[k] = bv; wsum += bv;
    }
    float inv = 1.f / wsum;
#pragma unroll
    for (int k = 0; k < TOPK; k++) {
        g_sel[t * TOPK + k]  = etmp[k];
        g_selw[t * TOPK + k] = wtmp[k] * inv;
        atomicAdd(&g_counts[etmp[k]], 1);
    }
}

__global__ void scan_kernel() {
    if (threadIdx.x == 0) {
        int s = 0;
        for (int e = 0; e < N_EXP; e++) { g_offsets[e] = s; s += g_counts[e]; }
        g_offsets[N_EXP] = s;
    }
}

__global__ void scatter_kernel() {
    int i = blockIdx.x * blockDim.x + threadIdx.x;
    if (i >= TK) return;
    int e = g_sel[i];
    int p = g_offsets[e] + atomicAdd(&g_fill[e], 1);
    g_toklist[p] = i / TOPK;
    g_pos[i] = p;
}

// combine: out[t] += sum_k w_k * dout_fp16[pos_k]; 8 halves (16B) per thread, blockDim 256
__global__ void combine_kernel(float* __restrict__ out) {
    int t = blockIdx.x;
    float w[TOPK]; int ps[TOPK];
#pragma unroll
    for (int k = 0; k < TOPK; k++) { w[k] = g_selw[t * TOPK + k]; ps[k] = g_pos[t * TOPK + k]; }
    int h8 = threadIdx.x * 8;    // blockDim 256 covers H_DIM=2048
    float* op = out + (size_t)t * H_DIM + h8;
    float4 o0 = *(float4*)(op);
    float4 o1 = *(float4*)(op + 4);
    float acc[8] = {o0.x, o0.y, o0.z, o0.w, o1.x, o1.y, o1.z, o1.w};
#pragma unroll
    for (int k = 0; k < TOPK; k++) {
        uint4 v = *(const uint4*)(g_dout + (size_t)ps[k] * H_DIM + h8);
        const __half2* hv = (const __half2*)&v;
#pragma unroll
        for (int j = 0; j < 4; j++) {
            float2 f = __half22float2(hv[j]);
            acc[2 * j]     += w[k] * f.x;
            acc[2 * j + 1] += w[k] * f.y;
        }
    }
    *(float4*)(op)     = make_float4(acc[0], acc[1], acc[2], acc[3]);
    *(float4*)(op + 4) = make_float4(acc[4], acc[5], acc[6], acc[7]);
}

// ---------------- FP16 mma.sync GEMM (round-6 best config) ----------------
// C[row][n] = sum_k A[arow][k] * B[k][n]
// Tile 128x128x32, 4 warps (2x2 grid, 64x64 warp tiles), 4-stage cp.async pipeline, 2 CTAs/SM.
#define BM 128
#define BN 128
#define BK 32
#define NTHR 128
#define ASTR 40      // halves per A smem row (64B data + 16B pad)
#define BSTR 136     // halves per B smem row (256B data + 16B pad)
#define A_BYTES (BM * ASTR * 2)          // 10240
#define B_BYTES (BK * BSTR * 2)          // 8704
#define STAGEB  (A_BYTES + B_BYTES)      // 18944
#define NSTAGE 4
#define SMEM_BYTES (NSTAGE * STAGEB)     // 75776

#define EPI_F  0
#define EPI_H  1
#define EPI_SP 2

template <bool EXPERT, bool GATHER, int EPI>
__global__ void __launch_bounds__(NTHR, 2)
hgemm(const __half* __restrict__ A, const __half* __restrict__ B0,
      void* __restrict__ Cv, int rowsTotal, int N, int K) {
    int e = EXPERT ? blockIdx.z : 0;
    int base = 0, cnt;
    if (EXPERT) { base = g_offsets[e]; cnt = g_offsets[e + 1] - base; }
    else        cnt = rowsTotal;
    int row0 = blockIdx.y * BM;
    if (row0 >= cnt) return;
    int n0 = blockIdx.x * BN;
    const __half* B = EXPERT ? B0 + (size_t)e * K * N : B0;
    const int Cw = (EPI == EPI_SP) ? (N >> 1) : N;

    extern __shared__ char smem[];
    uint32_t s0 = smem_u32(smem);

    int tid = threadIdx.x, wid = tid >> 5, lane = tid & 31;
    int wm = wid >> 1, wn = wid & 1;     // 2x2 warp grid, 64x64 warp tile

    // ---- hoisted loader addresses ----
    const __half* aptr[4]; uint32_t adst[4];
    const __half* bptr[4]; uint32_t bdst[4];
#pragma unroll
    for (int it = 0; it < 4; it++) {
        int i = tid + it * NTHR;
        int row = i >> 2, ch = i & 3;
        int r = min(row0 + row, cnt - 1);
        int arow = GATHER ? g_toklist[base + r] : (base + r);
        aptr[it] = A + (size_t)arow * K + ch * 8;
        adst[it] = (uint32_t)(row * ASTR + ch * 8) * 2;
    }
#pragma unroll
    for (int it = 0; it < 4; it++) {
        int i = tid + it * NTHR;
        int krow = i >> 4, ch = i & 15;
        bptr[it] = B + (size_t)krow * N + n0 + ch * 8;
        bdst[it] = (uint32_t)(krow * BSTR + ch * 8) * 2;
    }

    float acc[4][8][4];
#pragma unroll
    for (int mf = 0; mf < 4; mf++)
#pragma unroll
        for (int nf = 0; nf < 8; nf++)
#pragma unroll
            for (int q = 0; q < 4; q++) acc[mf][nf][q] = 0.f;

    const int nch = K / BK;

    auto load_stage = [&](int c, int s) {
        uint32_t sa = s0 + s * STAGEB;
        uint32_t sb = sa + A_BYTES;
        int ktA = c * BK;
        size_t ktB = (size_t)c * BK * N;
#pragma unroll
        for (int it = 0; it < 4; it++) CP16(sa + adst[it], aptr[it] + ktA);
#pragma unroll
        for (int it = 0; it < 4; it++) CP16(sb + bdst[it], bptr[it] + ktB);
        CP_COMMIT();
    };

    load_stage(0, 0);
    load_stage(1, 1);
    load_stage(2, 2);

    // ldmatrix per-thread offsets
    int a_row = lane & 15, a_k = (lane >> 4) * 8;
    int b_k = (lane & 7) + ((lane >> 3) & 1) * 8;
    int b_n = (lane >> 4) * 8;

    uint32_t af[2][4][4], bf[2][8][2];

    for (int c = 0; c < nch; c++) {
        int s = c & (NSTAGE - 1);
        int pend = nch - 1 - c;
        if (pend >= 2)      asm volatile("cp.async.wait_group 2;" ::: "memory");
        else if (pend == 1) asm volatile("cp.async.wait_group 1;" ::: "memory");
        else                asm volatile("cp.async.wait_group 0;" ::: "memory");
        __syncthreads();
        if (c + 3 < nch) load_stage(c + 3, (c + 3) & (NSTAGE - 1));

        uint32_t sa = s0 + s * STAGEB;
        uint32_t sb = sa + A_BYTES;

#pragma unroll
        for (int ks = 0; ks < 2; ks++) {
            int k0 = ks * 16;
#pragma unroll
            for (int mf = 0; mf < 4; mf++)
                ldsm4(af[ks][mf], sa + ((wm * 64 + mf * 16 + a_row) * ASTR + k0 + a_k) * 2);
#pragma unroll
            for (int p = 0; p < 4; p++) {
                uint32_t r[4];
                ldsm4t(r, sb + ((k0 + b_k) * BSTR + wn * 64 + p * 16 + b_n) * 2);
                bf[ks][2 * p][0] = r[0]; bf[ks][2 * p][1] = r[1];
                bf[ks][2 * p + 1][0] = r[2]; bf[ks][2 * p + 1][1] = r[3];
            }
        }
#pragma unroll
        for (int ks = 0; ks < 2; ks++)
#pragma unroll
            for (int mf = 0; mf < 4; mf++)
#pragma unroll
                for (int nf = 0; nf < 8; nf++)
                    mma_f16(acc[mf][nf], af[ks][mf], bf[ks][nf]);
    }

    // epilogue
    int gq = lane >> 2, tc4 = lane & 3;
#pragma unroll
    for (int mf = 0; mf < 4; mf++) {
        int rA = row0 + wm * 64 + mf * 16 + gq;
        int rB = rA + 8;
        bool vA = rA < cnt, vB = rB < cnt;
        size_t cra = EXPERT ? (size_t)(base + rA) : (size_t)rA;
        size_t crb = EXPERT ? (size_t)(base + rB) : (size_t)rB;
#pragma unroll
        for (int nf = 0; nf < 8; nf++) {
            int col = n0 + wn * 64 + nf * 8 + tc4 * 2;
            if (EPI == EPI_F) {
                float* C = (float*)Cv;
                if (vA) *(float2*)(C + cra * (size_t)Cw + col) = make_float2(acc[mf][nf][0], acc[mf][nf][1]);
                if (vB) *(float2*)(C + crb * (size_t)Cw + col) = make_float2(acc[mf][nf][2], acc[mf][nf][3]);
            } else if (EPI == EPI_H) {
                __half* C = (__half*)Cv;
                if (vA) *(__half2*)(C + cra * (size_t)Cw + col) = __floats2half2_rn(acc[mf][nf][0], acc[mf][nf][1]);
                if (vB) *(__half2*)(C + crb * (size_t)Cw + col) = __floats2half2_rn(acc[mf][nf][2], acc[mf][nf][3]);
            } else {  // EPI_SP: (gate,up) pair -> silu(g)*u
                __half* C = (__half*)Cv;
                int lcol = col >> 1;
                if (vA) C[cra * (size_t)Cw + lcol] = __float2half_rn(silu_mul(acc[mf][nf][0], acc[mf][nf][1]));
                if (vB) C[crb * (size_t)Cw + lcol] = __float2half_rn(silu_mul(acc[mf][nf][2], acc[mf][nf][3]));
            }
        }
    }
}

// ---------------- launch ----------------
extern "C" void kernel_launch(void* const* d_in, const int* in_sizes, int n_in,
                              void* d_out, int out_size) {
    const float* x   = (const float*)d_in[0];
    const float* gw  = (const float*)d_in[1];
    const float* wg  = (const float*)d_in[2];
    const float* wu  = (const float*)d_in[3];
    const float* wd  = (const float*)d_in[4];
    const float* swg = (const float*)d_in[5];
    const float* swu = (const float*)d_in[6];
    const float* swd = (const float*)d_in[7];
    float* out = (float*)d_out;

    __half *p_xh, *p_wguh, *p_wdh, *p_swguh, *p_swdh, *p_hr, *p_hs, *p_dout;
    cudaGetSymbolAddress((void**)&p_xh, g_xh);
    cudaGetSymbolAddress((void**)&p_wguh, g_wguh);
    cudaGetSymbolAddress((void**)&p_wdh, g_wdh);
    cudaGetSymbolAddress((void**)&p_swguh, g_swguh);
    cudaGetSymbolAddress((void**)&p_swdh, g_swdh);
    cudaGetSymbolAddress((void**)&p_hr, g_hr);
    cudaGetSymbolAddress((void**)&p_hs, g_hs);
    cudaGetSymbolAddress((void**)&p_dout, g_dout);

    cudaFuncSetAttribute(hgemm<false, false, EPI_SP>, cudaFuncAttributeMaxDynamicSharedMemorySize, SMEM_BYTES);
    cudaFuncSetAttribute(hgemm<false, false, EPI_F>,  cudaFuncAttributeMaxDynamicSharedMemorySize, SMEM_BYTES);
    cudaFuncSetAttribute(hgemm<true, true, EPI_SP>,   cudaFuncAttributeMaxDynamicSharedMemorySize, SMEM_BYTES);
    cudaFuncSetAttribute(hgemm<true, false, EPI_H>,   cudaFuncAttributeMaxDynamicSharedMemorySize, SMEM_BYTES);

    dim3 blk(256);
    dim3 gblk(NTHR);

    const size_t nW = (size_t)N_EXP * H_DIM * M_DIM;   // 92.3M
    const size_t nS = (size_t)H_DIM * SH_DIM;          // 5.77M

    // shared path first (keeps a GEMM at launch index 3 for the ncu window)
    cvt_f2h<<<(T_TOK * H_DIM) / 1024, blk>>>(x, p_xh);                 // 0
    cvt_interleave<<<(int)(nS / 1024), blk>>>(swg, swu, p_swguh);      // 1
    cvt_f2h<<<(int)(nS / 1024), blk>>>(swd, p_swdh);                   // 2
    hgemm<false, false, EPI_SP><<<dim3(2 * SH_DIM / BN, T_TOK / BM, 1), gblk, SMEM_BYTES>>>(
        p_xh, p_swguh, p_hs, T_TOK, 2 * SH_DIM, H_DIM);                // 3
    hgemm<false, false, EPI_F><<<dim3(H_DIM / BN, T_TOK / BM, 1), gblk, SMEM_BYTES>>>(
        p_hs, p_swdh, out, T_TOK, H_DIM, SH_DIM);                      // 4

    // routed-path converts + routing
    cvt_interleave<<<(int)(nW / 1024), blk>>>(wg, wu, p_wguh);
    cvt_f2h<<<(int)(nW / 1024), blk>>>(wd, p_wdh);
    reset_kernel<<<1, 64>>>();
    gate_kernel<<<(T_TOK * 32) / 256, blk>>>(x, gw);
    route_kernel<<<T_TOK / 256, blk>>>();
    scan_kernel<<<1, 32>>>();
    scatter_kernel<<<TK / 256, blk>>>();

    // routed experts: fused gate|up -> hr, down -> dout (fp16)
    hgemm<true, true, EPI_SP><<<dim3(2 * M_DIM / BN, T_TOK / BM, N_EXP), gblk, SMEM_BYTES>>>(
        p_xh, p_wguh, p_hr, TK, 2 * M_DIM, H_DIM);
    hgemm<true, false, EPI_H><<<dim3(H_DIM / BN, T_TOK / BM, N_EXP), gblk, SMEM_BYTES>>>(
        p_hr, p_wdh, p_dout, TK, H_DIM, M_DIM);

    // weighted combine of routed outputs into out
    combine_kernel<<<T_TOK, blk>>>(out);
}

// round 10
// speedup vs baseline: 1.3171x; 1.0138x over previous
#include <cuda_runtime.h>
#include <cuda_fp16.h>
#include <math.h>
#include <cstdint>

// ---------------- problem constants ----------------
#define T_TOK   8192
#define H_DIM   2048
#define N_EXP   32
#define TOPK    6
#define M_DIM   1408
#define SH_DIM  2816
#define TK      (T_TOK * TOPK)   // 49152

// ---------------- scratch (device globals) ----------------
__device__ __half g_xh[(size_t)T_TOK * H_DIM];            // fp16 x
__device__ __half g_wguh[(size_t)N_EXP * H_DIM * 2 * M_DIM];  // interleaved gate|up weights
__device__ __half g_wdh[(size_t)N_EXP * M_DIM * H_DIM];
__device__ __half g_swguh[(size_t)H_DIM * 2 * SH_DIM];    // interleaved shared gate|up
__device__ __half g_swdh[(size_t)SH_DIM * H_DIM];
__device__ __half g_hr[(size_t)TK * M_DIM];               // routed silu(g)*u
__device__ __half g_dout[(size_t)TK * H_DIM];             // routed down out (fp16)
__device__ __half g_hs[(size_t)T_TOK * SH_DIM];           // shared silu(g)*u
__device__ float  g_scores[T_TOK * N_EXP];
__device__ int    g_sel[TK];
__device__ float  g_selw[TK];
__device__ int    g_counts[N_EXP];
__device__ int    g_offsets[N_EXP + 1];
__device__ int    g_fill[N_EXP];
__device__ int    g_toklist[TK];
__device__ int    g_pos[TK];

// ---------------- PTX helpers ----------------
__device__ __forceinline__ uint32_t smem_u32(const void* p) {
    uint32_t a;
    asm("{ .reg .u64 t; cvta.to.shared.u64 t, %1; cvt.u32.u64 %0, t; }" : "=r"(a) : "l"(p));
    return a;
}
#define CP16(dst, src)  asm volatile("cp.async.cg.shared.global [%0], [%1], 16;" :: "r"(dst), "l"(src) : "memory")
#define CP_COMMIT()     asm volatile("cp.async.commit_group;" ::: "memory")

__device__ __forceinline__ void ldsm4(uint32_t* r, uint32_t addr) {
    asm volatile("ldmatrix.sync.aligned.m8n8.x4.shared.b16 {%0,%1,%2,%3}, [%4];"
                 : "=r"(r[0]), "=r"(r[1]), "=r"(r[2]), "=r"(r[3]) : "r"(addr));
}
__device__ __forceinline__ void ldsm4t(uint32_t* r, uint32_t addr) {
    asm volatile("ldmatrix.sync.aligned.m8n8.x4.trans.shared.b16 {%0,%1,%2,%3}, [%4];"
                 : "=r"(r[0]), "=r"(r[1]), "=r"(r[2]), "=r"(r[3]) : "r"(addr));
}
__device__ __forceinline__ void mma_f16(float* d, const uint32_t* a, const uint32_t* b) {
    asm volatile("mma.sync.aligned.m16n8k16.row.col.f32.f16.f16.f32 "
                 "{%0,%1,%2,%3}, {%4,%5,%6,%7}, {%8,%9}, {%0,%1,%2,%3};"
                 : "+f"(d[0]), "+f"(d[1]), "+f"(d[2]), "+f"(d[3])
                 : "r"(a[0]), "r"(a[1]), "r"(a[2]), "r"(a[3]), "r"(b[0]), "r"(b[1]));
}
__device__ __forceinline__ float silu_mul(float g, float u) {
    return g / (1.f + expf(-g)) * u;
}

// ---------------- small kernels ----------------
__global__ void reset_kernel() {
    int i = threadIdx.x;
    if (i < N_EXP) { g_counts[i] = 0; g_fill[i] = 0; }
}

// fp32 -> fp16, 4 elems/thread (n divisible by 1024): 1 LDG.128 + 1 STG.64
__global__ void cvt_f2h(const float* __restrict__ in, __half* __restrict__ out) {
    size_t i = ((size_t)blockIdx.x * blockDim.x + threadIdx.x) * 4;
    float4 v = *(const float4*)(in + i);
    __half2 h[2];
    h[0] = __floats2half2_rn(v.x, v.y);
    h[1] = __floats2half2_rn(v.z, v.w);
    *(uint2*)(out + i) = *(uint2*)h;
}

// interleave: out[2i]=a[i], out[2i+1]=b[i] as fp16, 4 inputs/thread: 2 LDG.128 + 1 STG.128
__global__ void cvt_interleave(const float* __restrict__ a, const float* __restrict__ b,
                               __half* __restrict__ out) {
    size_t i = ((size_t)blockIdx.x * blockDim.x + threadIdx.x) * 4;
    float4 av = *(const float4*)(a + i);
    float4 bv = *(const float4*)(b + i);
    __half2 h[4];
    h[0] = __floats2half2_rn(av.x, bv.x); h[1] = __floats2half2_rn(av.y, bv.y);
    h[2] = __floats2half2_rn(av.z, bv.z); h[3] = __floats2half2_rn(av.w, bv.w);
    *(uint4*)(out + 2 * i) = *(uint4*)h;
}

__global__ void gate_kernel(const float* __restrict__ x, const float* __restrict__ gw) {
    int warp = (blockIdx.x * blockDim.x + threadIdx.x) >> 5;
    int lane = threadIdx.x & 31;
    if (warp >= T_TOK) return;
    const float* xr = x + (size_t)warp * H_DIM;
    float acc = 0.f;
#pragma unroll 4
    for (int h = 0; h < H_DIM; h += 4) {
        float4 xv = *(const float4*)(xr + h);
        acc += xv.x * gw[(h + 0) * N_EXP + lane];
        acc += xv.y * gw[(h + 1) * N_EXP + lane];
        acc += xv.z * gw[(h + 2) * N_EXP + lane];
        acc += xv.w * gw[(h + 3) * N_EXP + lane];
    }
    g_scores[warp * N_EXP + lane] = 1.f / (1.f + expf(-acc));
}

__global__ void route_kernel() {
    int t = blockIdx.x * blockDim.x + threadIdx.x;
    if (t >= T_TOK) return;
    float sc[N_EXP];
#pragma unroll
    for (int e = 0; e < N_EXP; e++) sc[e] = g_scores[t * N_EXP + e];
    float gm[4];
#pragma unroll
    for (int g = 0; g < 4; g++) {
        float m = sc[g * 8];
#pragma unroll
        for (int j = 1; j < 8; j++) m = fmaxf(m, sc[g * 8 + j]);
        gm[g] = m;
    }
    int g1 = 0;
#pragma unroll
    for (int g = 1; g < 4; g++) if (gm[g] > gm[g1]) g1 = g;
    int g2 = (g1 == 0) ? 1 : 0;
#pragma unroll
    for (int g = 0; g < 4; g++) if (g != g1 && gm[g] > gm[g2]) g2 = g;
    unsigned allowed = 0;
#pragma unroll
    for (int e = 0; e < N_EXP; e++) {
        int g = e >> 3;
        if (g == g1 || g == g2) allowed |= (1u << e);
    }
    unsigned picked = 0;
    float wsum = 0.f;
    int etmp[TOPK]; float wtmp[TOPK];
#pragma unroll
    for (int k = 0; k < TOPK; k++) {
        int best = -1; float bv = -1.f;
#pragma unroll
        for (int e = 0; e < N_EXP; e++) {
            if (!((allowed >> e) & 1u)) continue;
            if ((picked >> e) & 1u) continue;
            if (sc[e] > bv) { bv = sc[e]; best = e; }
        }
        picked |= (1u << best);
        etmp[k] = best; wtmp[k] = bv; wsum += bv;
    }
    float inv = 1.f / wsum;
#pragma unroll
    for (int k = 0; k < TOPK; k++) {
        g_sel[t * TOPK + k]  = etmp[k];
        g_selw[t * TOPK + k] = wtmp[k] * inv;
        atomicAdd(&g_counts[etmp[k]], 1);
    }
}

__global__ void scan_kernel() {
    if (threadIdx.x == 0) {
        int s = 0;
        for (int e = 0; e < N_EXP; e++) { g_offsets[e] = s; s += g_counts[e]; }
        g_offsets[N_EXP] = s;
    }
}

__global__ void scatter_kernel() {
    int i = blockIdx.x * blockDim.x + threadIdx.x;
    if (i >= TK) return;
    int e = g_sel[i];
    int p = g_offsets[e] + atomicAdd(&g_fill[e], 1);
    g_toklist[p] = i / TOPK;
    g_pos[i] = p;
}

// combine: out[t] += sum_k w_k * dout_fp16[pos_k]; 8 halves (16B) per thread, blockDim 256
__global__ void combine_kernel(float* __restrict__ out) {
    int t = blockIdx.x;
    float w[TOPK]; int ps[TOPK];
#pragma unroll
    for (int k = 0; k < TOPK; k++) { w[k] = g_selw[t * TOPK + k]; ps[k] = g_pos[t * TOPK + k]; }
    int h8 = threadIdx.x * 8;    // blockDim 256 covers H_DIM=2048
    float* op = out + (size_t)t * H_DIM + h8;
    float4 o0 = *(float4*)(op);
    float4 o1 = *(float4*)(op + 4);
    float acc[8] = {o0.x, o0.y, o0.z, o0.w, o1.x, o1.y, o1.z, o1.w};
#pragma unroll
    for (int k = 0; k < TOPK; k++) {
        uint4 v = *(const uint4*)(g_dout + (size_t)ps[k] * H_DIM + h8);
        const __half2* hv = (const __half2*)&v;
#pragma unroll
        for (int j = 0; j < 4; j++) {
            float2 f = __half22float2(hv[j]);
            acc[2 * j]     += w[k] * f.x;
            acc[2 * j + 1] += w[k] * f.y;
        }
    }
    *(float4*)(op)     = make_float4(acc[0], acc[1], acc[2], acc[3]);
    *(float4*)(op + 4) = make_float4(acc[4], acc[5], acc[6], acc[7]);
}

// ---------------- FP16 mma.sync GEMM (best config: R6 core + lb(128,2)) ----------------
// C[row][n] = sum_k A[arow][k] * B[k][n]
// Tile 128x128x32, 4 warps (2x2 grid, 64x64 warp tiles), 4-stage cp.async pipeline, 2 CTAs/SM.
#define BM 128
#define BN 128
#define BK 32
#define NTHR 128
#define ASTR 40      // halves per A smem row (64B data + 16B pad)
#define BSTR 136     // halves per B smem row (256B data + 16B pad)
#define A_BYTES (BM * ASTR * 2)          // 10240
#define B_BYTES (BK * BSTR * 2)          // 8704
#define STAGEB  (A_BYTES + B_BYTES)      // 18944
#define NSTAGE 4
#define SMEM_BYTES (NSTAGE * STAGEB)     // 75776

#define EPI_F  0
#define EPI_H  1
#define EPI_SP 2

template <bool EXPERT, bool GATHER, int EPI>
__global__ void __launch_bounds__(NTHR, 2)
hgemm(const __half* __restrict__ A, const __half* __restrict__ B0,
      void* __restrict__ Cv, int rowsTotal, int N, int K) {
    int e = EXPERT ? blockIdx.z : 0;
    int base = 0, cnt;
    if (EXPERT) { base = g_offsets[e]; cnt = g_offsets[e + 1] - base; }
    else        cnt = rowsTotal;
    int row0 = blockIdx.y * BM;
    if (row0 >= cnt) return;
    int n0 = blockIdx.x * BN;
    const __half* B = EXPERT ? B0 + (size_t)e * K * N : B0;
    const int Cw = (EPI == EPI_SP) ? (N >> 1) : N;

    extern __shared__ char smem[];
    uint32_t s0 = smem_u32(smem);

    int tid = threadIdx.x, wid = tid >> 5, lane = tid & 31;
    int wm = wid >> 1, wn = wid & 1;     // 2x2 warp grid, 64x64 warp tile

    // ---- hoisted loader addresses ----
    const __half* aptr[4]; uint32_t adst[4];
    const __half* bptr[4]; uint32_t bdst[4];
#pragma unroll
    for (int it = 0; it < 4; it++) {
        int i = tid + it * NTHR;
        int row = i >> 2, ch = i & 3;
        int r = min(row0 + row, cnt - 1);
        int arow = GATHER ? g_toklist[base + r] : (base + r);
        aptr[it] = A + (size_t)arow * K + ch * 8;
        adst[it] = (uint32_t)(row * ASTR + ch * 8) * 2;
    }
#pragma unroll
    for (int it = 0; it < 4; it++) {
        int i = tid + it * NTHR;
        int krow = i >> 4, ch = i & 15;
        bptr[it] = B + (size_t)krow * N + n0 + ch * 8;
        bdst[it] = (uint32_t)(krow * BSTR + ch * 8) * 2;
    }

    float acc[4][8][4];
#pragma unroll
    for (int mf = 0; mf < 4; mf++)
#pragma unroll
        for (int nf = 0; nf < 8; nf++)
#pragma unroll
            for (int q = 0; q < 4; q++) acc[mf][nf][q] = 0.f;

    const int nch = K / BK;

    auto load_stage = [&](int c, int s) {
        uint32_t sa = s0 + s * STAGEB;
        uint32_t sb = sa + A_BYTES;
        int ktA = c * BK;
        size_t ktB = (size_t)c * BK * N;
#pragma unroll
        for (int it = 0; it < 4; it++) CP16(sa + adst[it], aptr[it] + ktA);
#pragma unroll
        for (int it = 0; it < 4; it++) CP16(sb + bdst[it], bptr[it] + ktB);
        CP_COMMIT();
    };

    load_stage(0, 0);
    load_stage(1, 1);
    load_stage(2, 2);

    // ldmatrix per-thread offsets
    int a_row = lane & 15, a_k = (lane >> 4) * 8;
    int b_k = (lane & 7) + ((lane >> 3) & 1) * 8;
    int b_n = (lane >> 4) * 8;

    uint32_t af[2][4][4], bf[2][8][2];

    for (int c = 0; c < nch; c++) {
        int s = c & (NSTAGE - 1);
        int pend = nch - 1 - c;
        if (pend >= 2)      asm volatile("cp.async.wait_group 2;" ::: "memory");
        else if (pend == 1) asm volatile("cp.async.wait_group 1;" ::: "memory");
        else                asm volatile("cp.async.wait_group 0;" ::: "memory");
        __syncthreads();
        if (c + 3 < nch) load_stage(c + 3, (c + 3) & (NSTAGE - 1));

        uint32_t sa = s0 + s * STAGEB;
        uint32_t sb = sa + A_BYTES;

#pragma unroll
        for (int ks = 0; ks < 2; ks++) {
            int k0 = ks * 16;
#pragma unroll
            for (int mf = 0; mf < 4; mf++)
                ldsm4(af[ks][mf], sa + ((wm * 64 + mf * 16 + a_row) * ASTR + k0 + a_k) * 2);
#pragma unroll
            for (int p = 0; p < 4; p++) {
                uint32_t r[4];
                ldsm4t(r, sb + ((k0 + b_k) * BSTR + wn * 64 + p * 16 + b_n) * 2);
                bf[ks][2 * p][0] = r[0]; bf[ks][2 * p][1] = r[1];
                bf[ks][2 * p + 1][0] = r[2]; bf[ks][2 * p + 1][1] = r[3];
            }
        }
#pragma unroll
        for (int ks = 0; ks < 2; ks++)
#pragma unroll
            for (int mf = 0; mf < 4; mf++)
#pragma unroll
                for (int nf = 0; nf < 8; nf++)
                    mma_f16(acc[mf][nf], af[ks][mf], bf[ks][nf]);
    }

    // epilogue
    int gq = lane >> 2, tc4 = lane & 3;
#pragma unroll
    for (int mf = 0; mf < 4; mf++) {
        int rA = row0 + wm * 64 + mf * 16 + gq;
        int rB = rA + 8;
        bool vA = rA < cnt, vB = rB < cnt;
        size_t cra = EXPERT ? (size_t)(base + rA) : (size_t)rA;
        size_t crb = EXPERT ? (size_t)(base + rB) : (size_t)rB;
#pragma unroll
        for (int nf = 0; nf < 8; nf++) {
            int col = n0 + wn * 64 + nf * 8 + tc4 * 2;
            if (EPI == EPI_F) {
                float* C = (float*)Cv;
                if (vA) *(float2*)(C + cra * (size_t)Cw + col) = make_float2(acc[mf][nf][0], acc[mf][nf][1]);
                if (vB) *(float2*)(C + crb * (size_t)Cw + col) = make_float2(acc[mf][nf][2], acc[mf][nf][3]);
            } else if (EPI == EPI_H) {
                __half* C = (__half*)Cv;
                if (vA) *(__half2*)(C + cra * (size_t)Cw + col) = __floats2half2_rn(acc[mf][nf][0], acc[mf][nf][1]);
                if (vB) *(__half2*)(C + crb * (size_t)Cw + col) = __floats2half2_rn(acc[mf][nf][2], acc[mf][nf][3]);
            } else {  // EPI_SP: (gate,up) pair -> silu(g)*u
                __half* C = (__half*)Cv;
                int lcol = col >> 1;
                if (vA) C[cra * (size_t)Cw + lcol] = __float2half_rn(silu_mul(acc[mf][nf][0], acc[mf][nf][1]));
                if (vB) C[crb * (size_t)Cw + lcol] = __float2half_rn(silu_mul(acc[mf][nf][2], acc[mf][nf][3]));
            }
        }
    }
}

// ---------------- launch ----------------
extern "C" void kernel_launch(void* const* d_in, const int* in_sizes, int n_in,
                              void* d_out, int out_size) {
    const float* x   = (const float*)d_in[0];
    const float* gw  = (const float*)d_in[1];
    const float* wg  = (const float*)d_in[2];
    const float* wu  = (const float*)d_in[3];
    const float* wd  = (const float*)d_in[4];
    const float* swg = (const float*)d_in[5];
    const float* swu = (const float*)d_in[6];
    const float* swd = (const float*)d_in[7];
    float* out = (float*)d_out;

    __half *p_xh, *p_wguh, *p_wdh, *p_swguh, *p_swdh, *p_hr, *p_hs, *p_dout;
    cudaGetSymbolAddress((void**)&p_xh, g_xh);
    cudaGetSymbolAddress((void**)&p_wguh, g_wguh);
    cudaGetSymbolAddress((void**)&p_wdh, g_wdh);
    cudaGetSymbolAddress((void**)&p_swguh, g_swguh);
    cudaGetSymbolAddress((void**)&p_swdh, g_swdh);
    cudaGetSymbolAddress((void**)&p_hr, g_hr);
    cudaGetSymbolAddress((void**)&p_hs, g_hs);
    cudaGetSymbolAddress((void**)&p_dout, g_dout);

    cudaFuncSetAttribute(hgemm<false, false, EPI_SP>, cudaFuncAttributeMaxDynamicSharedMemorySize, SMEM_BYTES);
    cudaFuncSetAttribute(hgemm<false, false, EPI_F>,  cudaFuncAttributeMaxDynamicSharedMemorySize, SMEM_BYTES);
    cudaFuncSetAttribute(hgemm<true, true, EPI_SP>,   cudaFuncAttributeMaxDynamicSharedMemorySize, SMEM_BYTES);
    cudaFuncSetAttribute(hgemm<true, false, EPI_H>,   cudaFuncAttributeMaxDynamicSharedMemorySize, SMEM_BYTES);

    // one-time host-side setup: side stream + fork/join events (no device memory)
    static cudaStream_t s_side = nullptr;
    static cudaEvent_t s_evFork = nullptr, s_evJoin = nullptr;
    if (s_side == nullptr) {
        cudaStreamCreateWithFlags(&s_side, cudaStreamNonBlocking);
        cudaEventCreateWithFlags(&s_evFork, cudaEventDisableTiming);
        cudaEventCreateWithFlags(&s_evJoin, cudaEventDisableTiming);
    }

    dim3 blk(256);
    dim3 gblk(NTHR);

    const size_t nW = (size_t)N_EXP * H_DIM * M_DIM;   // 92.3M
    const size_t nS = (size_t)H_DIM * SH_DIM;          // 5.77M

    // ---- fork: side stream handles routed-path prep (weight converts + routing) ----
    cudaEventRecord(s_evFork, 0);
    cudaStreamWaitEvent(s_side, s_evFork, 0);

    // side stream: big weight converts + routing chain (independent of shared path)
    cvt_interleave<<<(int)(nW / 1024), blk, 0, s_side>>>(wg, wu, p_wguh);
    cvt_f2h<<<(int)(nW / 1024), blk, 0, s_side>>>(wd, p_wdh);
    reset_kernel<<<1, 64, 0, s_side>>>();
    gate_kernel<<<(T_TOK * 32) / 256, blk, 0, s_side>>>(x, gw);
    route_kernel<<<T_TOK / 256, blk, 0, s_side>>>();
    scan_kernel<<<1, 32, 0, s_side>>>();
    scatter_kernel<<<TK / 256, blk, 0, s_side>>>();
    cudaEventRecord(s_evJoin, s_side);

    // main stream: shared-expert path
    cvt_f2h<<<(T_TOK * H_DIM) / 1024, blk>>>(x, p_xh);
    cvt_interleave<<<(int)(nS / 1024), blk>>>(swg, swu, p_swguh);
    cvt_f2h<<<(int)(nS / 1024), blk>>>(swd, p_swdh);
    hgemm<false, false, EPI_SP><<<dim3(2 * SH_DIM / BN, T_TOK / BM, 1), gblk, SMEM_BYTES>>>(
        p_xh, p_swguh, p_hs, T_TOK, 2 * SH_DIM, H_DIM);
    hgemm<false, false, EPI_F><<<dim3(H_DIM / BN, T_TOK / BM, 1), gblk, SMEM_BYTES>>>(
        p_hs, p_swdh, out, T_TOK, H_DIM, SH_DIM);

    // ---- join: routed GEMMs need wguh/wdh/toklist from the side stream ----
    cudaStreamWaitEvent(0, s_evJoin, 0);

    // routed experts: fused gate|up -> hr, down -> dout (fp16)
    hgemm<true, true, EPI_SP><<<dim3(2 * M_DIM / BN, T_TOK / BM, N_EXP), gblk, SMEM_BYTES>>>(
        p_xh, p_wguh, p_hr, TK, 2 * M_DIM, H_DIM);
    hgemm<true, false, EPI_H><<<dim3(H_DIM / BN, T_TOK / BM, N_EXP), gblk, SMEM_BYTES>>>(
        p_hr, p_wdh, p_dout, TK, H_DIM, M_DIM);

    // weighted combine of routed outputs into out
    combine_kernel<<<T_TOK, blk>>>(out);
}